// round 9
// baseline (speedup 1.0000x reference)
#include <cuda_runtime.h>
#include <cuda_fp16.h>
#include <cstdint>
#include <math.h>

// ---------------- problem constants ----------------
#define Bc 1024   // batch
#define Tc 40     // timesteps
#define Ec 512    // embed dim
#define Hc 1024   // hidden
#define Lc 256    // latent out
#define Ac 2048   // feature dim
#define Vc 30000  // vocab
#define Nw 4096   // 4*H
#define GRP 32    // CTAs per bm-group (barrier granularity)

// ---------------- device scratch (no allocation) ----------------
__device__ __half g_Wcat [2 * Hc * Ac];
__device__ float  g_bcat [2 * Hc];
__device__ __half g_Wocat[2 * Lc * Hc];
__device__ float  g_bocat[2 * Lc];
__device__ __half g_Wp   [Nw * (Hc + Ec)];
__device__ float  g_pb   [Nw];
__device__ __half g_hbuf [2][Bc * Hc];
__device__ float  g_c0   [Bc * Hc];
__device__ __half g_hl   [Bc * Hc];
__device__ __half g_embH [Vc * Ec];
__device__ __half g_ftH  [Bc * Ac];
__device__ unsigned int g_counters[8];    // per-bm-group step barriers

// ---------------- helpers ----------------
__device__ __forceinline__ uint32_t smem_u32(const void* p) {
    uint32_t a;
    asm("{ .reg .u64 t; cvta.to.shared.u64 t, %1; cvt.u32.u64 %0, t; }" : "=r"(a) : "l"(p));
    return a;
}
#define CP_ASYNC16(dst, src) \
    asm volatile("cp.async.cg.shared.global [%0], [%1], 16;" :: "r"(dst), "l"(src))
#define CP_COMMIT() asm volatile("cp.async.commit_group;" ::: "memory")
#define CP_WAIT2()  asm volatile("cp.async.wait_group 2;" ::: "memory")

__device__ __forceinline__ void mma_f16(float* d, const uint32_t* a, const uint32_t* b) {
    asm volatile(
        "mma.sync.aligned.m16n8k16.row.col.f32.f16.f16.f32 "
        "{%0,%1,%2,%3}, {%4,%5,%6,%7}, {%8,%9}, {%0,%1,%2,%3};"
        : "+f"(d[0]), "+f"(d[1]), "+f"(d[2]), "+f"(d[3])
        : "r"(a[0]), "r"(a[1]), "r"(a[2]), "r"(a[3]), "r"(b[0]), "r"(b[1]));
}
__device__ __forceinline__ void ldsm_x4(uint32_t* r, uint32_t addr) {
    asm volatile("ldmatrix.sync.aligned.m8n8.x4.shared.b16 {%0,%1,%2,%3}, [%4];"
        : "=r"(r[0]), "=r"(r[1]), "=r"(r[2]), "=r"(r[3]) : "r"(addr));
}
__device__ __forceinline__ float fex2(float x) { float r; asm("ex2.approx.f32 %0, %1;" : "=f"(r) : "f"(x)); return r; }
__device__ __forceinline__ float frcp(float x) { float r; asm("rcp.approx.f32 %0, %1;" : "=f"(r) : "f"(x)); return r; }
__device__ __forceinline__ float fsig(float x)  { return frcp(1.f + fex2(-1.4426950408889634f * x)); }
__device__ __forceinline__ float ftanh(float x) { return 1.f - 2.f * frcp(1.f + fex2(2.8853900817779268f * x)); }

// ---------------- prep kernels ----------------
__global__ void wn_kernel(const float* __restrict__ v, const float* __restrict__ g,
                          __half* __restrict__ W, int cols) {
    int r = blockIdx.x;
    const float* vr = v + (size_t)r * cols;
    float s = 0.f;
    for (int c = threadIdx.x; c < cols; c += blockDim.x) { float x = vr[c]; s += x * x; }
    __shared__ float sh[32];
    for (int o = 16; o > 0; o >>= 1) s += __shfl_down_sync(0xffffffffu, s, o);
    if ((threadIdx.x & 31) == 0) sh[threadIdx.x >> 5] = s;
    __syncthreads();
    if (threadIdx.x < 32) {
        float t = (threadIdx.x < (blockDim.x >> 5)) ? sh[threadIdx.x] : 0.f;
        for (int o = 16; o > 0; o >>= 1) t += __shfl_down_sync(0xffffffffu, t, o);
        if (threadIdx.x == 0) sh[0] = t;
    }
    __syncthreads();
    float scale = g[r] / sqrtf(sh[0]);
    __half* Wr = W + (size_t)r * cols;
    for (int c = threadIdx.x; c < cols; c += blockDim.x) Wr[c] = __float2half_rn(vr[c] * scale);
}

__global__ void permute_kernel(const float* __restrict__ Whh, const float* __restrict__ Wih,
                               const float* __restrict__ bih, const float* __restrict__ bhh,
                               __half* __restrict__ Wp, float* __restrict__ pb) {
    int n = blockIdx.x;
    int gt = n >> 10, j = n & 1023;
    int np = (j << 2) | gt;
    __half* dst = Wp + (size_t)np * (Hc + Ec);
    const float* s1 = Whh + (size_t)n * Hc;
    const float* s2 = Wih + (size_t)n * Ec;
    for (int k = threadIdx.x; k < Hc; k += blockDim.x) dst[k] = __float2half_rn(s1[k]);
    for (int k = threadIdx.x; k < Ec; k += blockDim.x) dst[Hc + k] = __float2half_rn(s2[k]);
    if (threadIdx.x == 0) pb[np] = bih[n] + bhh[n];
}

__global__ void half_copy(const float* __restrict__ src, __half* __restrict__ dst, int n) {
    int i = blockIdx.x * blockDim.x + threadIdx.x;
    if (i < n) dst[i] = __float2half_rn(src[i]);
}

__global__ void pack2(const float* __restrict__ a, const float* __restrict__ b,
                      float* __restrict__ dst, int n) {
    int i = blockIdx.x * blockDim.x + threadIdx.x;
    if (i < n) dst[i] = a[i];
    else if (i < 2 * n) dst[i] = b[i - n];
}

// ---------------- fp16 mma.sync GEMM (init / output projections) ----------------
static constexpr int ST    = 128 * 80;                    // 10240 B per stage
static constexpr int A_OFF = 1024;
static constexpr int B_OFF = A_OFF + 4 * ST;
static constexpr int SMEM_G = B_OFF + 4 * ST;             // 82944

__global__ __launch_bounds__(256, 2)
void hgemm(const __half* __restrict__ A1, int lda1, int kc1,
           const __half* __restrict__ Bw, int ldb,
           const float* __restrict__ bias,
           float* __restrict__ C1, int ldc1, int half1,
           float* __restrict__ C2, int ldc2, int half2, int ncut)
{
    extern __shared__ __align__(1024) char smem[];
    uint32_t sb = smem_u32(smem);
    int tid = threadIdx.x, wid = tid >> 5, lid = tid & 31;
    int g = lid >> 2, tig = lid & 3;
    int warpM = (wid & 1) * 64, warpN = (wid >> 1) * 32;
    int bm = blockIdx.y * 128, bn = blockIdx.x * 128;
    const int NC = kc1;

    uint32_t offA[4], offB[2];
#pragma unroll
    for (int rb = 0; rb < 4; rb++)
        offA[rb] = (warpM + rb * 16 + (lid & 15)) * 80 + (lid >> 4) * 16;
#pragma unroll
    for (int p = 0; p < 2; p++)
        offB[p] = (warpN + p * 16 + ((lid >> 4) << 3) + (lid & 7)) * 80 + ((lid >> 3) & 1) * 16;

    float acc[4][4][4];
#pragma unroll
    for (int i = 0; i < 4; i++)
#pragma unroll
        for (int j = 0; j < 4; j++)
#pragma unroll
            for (int q = 0; q < 4; q++) acc[i][j][q] = 0.f;

    auto load_chunk = [&](int c, int s) {
        uint32_t aB = sb + A_OFF + s * ST;
        uint32_t bB = sb + B_OFF + s * ST;
#pragma unroll
        for (int i = 0; i < 2; i++) {
            int seg = tid + i * 256;
            int m = seg >> 2, sg = seg & 3;
            CP_ASYNC16(aB + m * 80 + sg * 16, A1 + (size_t)(bm + m) * lda1 + c * 32 + sg * 8);
        }
#pragma unroll
        for (int i = 0; i < 2; i++) {
            int seg = tid + i * 256;
            int n = seg >> 2, sg = seg & 3;
            CP_ASYNC16(bB + n * 80 + sg * 16, Bw + (size_t)(bn + n) * ldb + c * 32 + sg * 8);
        }
    };

    for (int p = 0; p < 3; p++) { load_chunk(p, p); CP_COMMIT(); }

    for (int c = 0; c < NC; c++) {
        int s = c & 3;
        CP_WAIT2();
        __syncthreads();
        if (c + 3 < NC) load_chunk(c + 3, (c + 3) & 3);
        CP_COMMIT();
        uint32_t aB = sb + A_OFF + s * ST;
        uint32_t bB = sb + B_OFF + s * ST;
#pragma unroll
        for (int k16 = 0; k16 < 2; k16++) {
            uint32_t afr[4][4], bfr[2][4];
#pragma unroll
            for (int rb = 0; rb < 4; rb++) ldsm_x4(afr[rb], aB + offA[rb] + k16 * 32);
#pragma unroll
            for (int p = 0; p < 2; p++) ldsm_x4(bfr[p], bB + offB[p] + k16 * 32);
#pragma unroll
            for (int rb = 0; rb < 4; rb++) {
                mma_f16(acc[rb][0], afr[rb], &bfr[0][0]);
                mma_f16(acc[rb][1], afr[rb], &bfr[0][2]);
                mma_f16(acc[rb][2], afr[rb], &bfr[1][0]);
                mma_f16(acc[rb][3], afr[rb], &bfr[1][2]);
            }
        }
    }

    float* Cd; int cb, ldc, hf;
    if (bn < ncut) { Cd = C1; cb = bn;        ldc = ldc1; hf = half1; }
    else           { Cd = C2; cb = bn - ncut; ldc = ldc2; hf = half2; }
#pragma unroll
    for (int rb = 0; rb < 4; rb++) {
#pragma unroll
        for (int nb = 0; nb < 4; nb++) {
            int coll = warpN + nb * 8 + 2 * tig;
            int col = cb + coll;
            int r0 = bm + warpM + rb * 16 + g;
            float b0 = bias[bn + coll], b1 = bias[bn + coll + 1];
            float v0 = acc[rb][nb][0] + b0, v1 = acc[rb][nb][1] + b1;
            float v2 = acc[rb][nb][2] + b0, v3 = acc[rb][nb][3] + b1;
            if (hf) {
                __half* Ch = (__half*)Cd;
                *(__half2*)(Ch + (size_t)r0 * ldc + col)       = __floats2half2_rn(v0, v1);
                *(__half2*)(Ch + (size_t)(r0 + 8) * ldc + col) = __floats2half2_rn(v2, v3);
            } else {
                *(float2*)(Cd + (size_t)r0 * ldc + col)       = make_float2(v0, v1);
                *(float2*)(Cd + (size_t)(r0 + 8) * ldc + col) = make_float2(v2, v3);
            }
        }
    }
}

// ---------------- persistent LSTM recurrence ----------------
// smem: [0,1024) stok[2][128], [A_OFF, +8*ST) pipeline stages,
// h staging overlays stage-3 A region, c state + cap_len after stages.
static constexpr int CS_OFF = A_OFF + 8 * ST;             // 82944
static constexpr int CL_OFF = CS_OFF + 128 * 33 * 4;      // +16896 = 99840
static constexpr int SMEM_P = CL_OFF + 512;               // 100352
static constexpr int HS_OFF = A_OFF + 3 * ST;             // h staging (8704 B <= ST)

__global__ __launch_bounds__(256, 2)
void lstm_persist(const __half* __restrict__ embH,
                  const int* __restrict__ cap,
                  const __half* __restrict__ Wp,
                  const float* __restrict__ pb,
                  const float* __restrict__ c0,
                  __half* __restrict__ hbuf,
                  __half* __restrict__ hlast,
                  const int* __restrict__ cap_len,
                  unsigned int* __restrict__ counters)
{
    extern __shared__ __align__(1024) char smem[];
    uint32_t sb = smem_u32(smem);
    int tid = threadIdx.x, wid = tid >> 5, lid = tid & 31;
    int g = lid >> 2, tig = lid & 3;
    int warpM = (wid & 1) * 64, warpN = (wid >> 1) * 32;
    int bn = blockIdx.x * 128, bm = blockIdx.y * 128;
    int jg0 = bn >> 2;
    int* stok0 = (int*)smem;
    int* stok1 = (int*)(smem + 512);
    int* cl_s  = (int*)(smem + CL_OFF);
    float*  c_s = (float*)(smem + CS_OFF);
    __half* hsm = (__half*)(smem + HS_OFF);
    unsigned int* myctr = counters + blockIdx.y;

    uint32_t offA[4], offB[2];
#pragma unroll
    for (int rb = 0; rb < 4; rb++)
        offA[rb] = (warpM + rb * 16 + (lid & 15)) * 80 + (lid >> 4) * 16;
#pragma unroll
    for (int p = 0; p < 2; p++)
        offB[p] = (warpN + p * 16 + ((lid >> 4) << 3) + (lid & 7)) * 80 + ((lid >> 3) & 1) * 16;

    for (int idx = tid; idx < 128 * 32; idx += 256) {
        int row = idx >> 5, jl = idx & 31;
        c_s[row * 33 + jl] = c0[(size_t)(bm + row) * Hc + jg0 + jl];
    }
    if (tid < 128) {
        cl_s[tid]  = cap_len[bm + tid];
        stok0[tid] = cap[(size_t)(bm + tid) * Tc + 0];
    }
    __syncthreads();

    auto load_chunk = [&](const __half* hin, const int* tok, int c, int s) {
        uint32_t aB = sb + A_OFF + s * ST;
        uint32_t bB = sb + A_OFF + 4 * ST + s * ST;
#pragma unroll
        for (int i = 0; i < 2; i++) {
            int seg = tid + i * 256;
            int m = seg >> 2, sg = seg & 3;
            const __half* src = (c < 16)
                ? embH + (size_t)tok[m] * Ec + c * 32 + sg * 8
                : hin + (size_t)(bm + m) * Hc + (c - 16) * 32 + sg * 8;
            CP_ASYNC16(aB + m * 80 + sg * 16, src);
        }
#pragma unroll
        for (int i = 0; i < 2; i++) {
            int seg = tid + i * 256;
            int n = seg >> 2, sg = seg & 3;
            int kk = (c < 16) ? (Hc + c * 32) : ((c - 16) * 32);
            CP_ASYNC16(bB + n * 80 + sg * 16,
                       Wp + (size_t)(bn + n) * (Hc + Ec) + kk + sg * 8);
        }
    };

    // prologue for t=0: 3 embed chunks
    for (int p = 0; p < 3; p++) { load_chunk(nullptr, stok0, p, p); CP_COMMIT(); }

    for (int t = 0; t < Tc; t++) {
        const int* tok_cur  = (t & 1) ? stok1 : stok0;
        int*       tok_next = (t & 1) ? stok0 : stok1;
        const __half* hin  = hbuf + (size_t)(t & 1) * (Bc * Hc);
        __half*       hout = hbuf + (size_t)((t + 1) & 1) * (Bc * Hc);

        float acc[4][4][4];
#pragma unroll
        for (int i = 0; i < 4; i++)
#pragma unroll
            for (int j = 0; j < 4; j++)
#pragma unroll
                for (int q = 0; q < 4; q++) acc[i][j][q] = 0.f;

        for (int c = 0; c < 48; c++) {
            if (c == 13) {  // group barrier before first h-chunk load (chunk 16)
                if (tid == 0) {
                    unsigned int target = (unsigned int)(GRP * t);
                    unsigned int v;
                    do {
                        asm volatile("ld.acquire.gpu.global.u32 %0, [%1];"
                                     : "=r"(v) : "l"(myctr) : "memory");
                    } while (v < target);
                }
                __syncthreads();
            }
            if (c == 14 && t + 1 < Tc && tid < 128)
                tok_next[tid] = cap[(size_t)(bm + tid) * Tc + t + 1];
            int s = c & 3;
            CP_WAIT2();
            __syncthreads();
            if (c + 3 < 48) load_chunk(hin, tok_cur, c + 3, (c + 3) & 3);
            CP_COMMIT();
            uint32_t aB = sb + A_OFF + s * ST;
            uint32_t bB = sb + A_OFF + 4 * ST + s * ST;
#pragma unroll
            for (int k16 = 0; k16 < 2; k16++) {
                uint32_t afr[4][4], bfr[2][4];
#pragma unroll
                for (int rb = 0; rb < 4; rb++) ldsm_x4(afr[rb], aB + offA[rb] + k16 * 32);
#pragma unroll
                for (int p = 0; p < 2; p++) ldsm_x4(bfr[p], bB + offB[p] + k16 * 32);
#pragma unroll
                for (int rb = 0; rb < 4; rb++) {
                    mma_f16(acc[rb][0], afr[rb], &bfr[0][0]);
                    mma_f16(acc[rb][1], afr[rb], &bfr[0][2]);
                    mma_f16(acc[rb][2], afr[rb], &bfr[1][0]);
                    mma_f16(acc[rb][3], afr[rb], &bfr[1][2]);
                }
            }
        }

        // all warps done reading stages; prologue next step's embed chunks NOW
        __syncthreads();
        if (t + 1 < Tc) {
            for (int p = 0; p < 3; p++) { load_chunk(nullptr, tok_next, p, p); CP_COMMIT(); }
        }

        // shuffle epilogue: gates stay in registers; c in smem; stage only h
#pragma unroll
        for (int rb = 0; rb < 4; rb++) {
#pragma unroll
            for (int nb = 0; nb < 4; nb++) {
                int r0 = warpM + rb * 16 + g;
                float v0 = acc[rb][nb][0], v1 = acc[rb][nb][1];
                float v2 = acc[rb][nb][2], v3 = acc[rb][nb][3];
                bool ev = (tig & 1) == 0;
                float x = ev ? v2 : v0, y = ev ? v3 : v1;
                float px = __shfl_xor_sync(0xffffffffu, x, 1);
                float py = __shfl_xor_sync(0xffffffffu, y, 1);
                float gi = ev ? v0 : px, gf = ev ? v1 : py;
                float gg = ev ? px : v2, go = ev ? py : v3;
                int rrow = ev ? r0 : (r0 + 8);
                int Jl = (warpN >> 2) + 2 * nb + (tig >> 1);
                float4 pbv = *(const float4*)(pb + 4 * (jg0 + Jl));
                float si = fsig(gi + pbv.x);
                float sf = fsig(gf + pbv.y);
                float tg = ftanh(gg + pbv.z);
                float so = fsig(go + pbv.w);
                int ci = rrow * 33 + Jl;
                float cn = sf * c_s[ci] + si * tg;
                c_s[ci] = cn;
                hsm[rrow * 34 + Jl] = __float2half_rn(so * ftanh(cn));
            }
        }
        __syncthreads();
        for (int idx = tid; idx < 128 * 32; idx += 256) {
            int row = idx >> 5, jl = idx & 31;
            __half hv = hsm[row * 34 + jl];
            size_t off = (size_t)(bm + row) * Hc + jg0 + jl;
            hout[off] = hv;
            if (cl_s[row] - 1 == t) hlast[off] = hv;
        }
        __syncthreads();
        if (tid == 0)
            asm volatile("red.release.gpu.global.add.u32 [%0], %1;"
                         :: "l"(myctr), "r"(1u) : "memory");
    }
}

// ---------------- launch ----------------
extern "C" void kernel_launch(void* const* d_in, const int* in_sizes, int n_in,
                              void* d_out, int out_size) {
    const int*   cap     = (const int*)  d_in[0];
    const int*   cap_len = (const int*)  d_in[1];
    const float* feat    = (const float*)d_in[2];
    const float* embed   = (const float*)d_in[3];
    const float* W_ih    = (const float*)d_in[4];
    const float* W_hh    = (const float*)d_in[5];
    const float* b_ih    = (const float*)d_in[6];
    const float* b_hh    = (const float*)d_in[7];
    const float* v_ih0   = (const float*)d_in[8];
    const float* g_ih0   = (const float*)d_in[9];
    const float* b_ih0   = (const float*)d_in[10];
    const float* v_ic0   = (const float*)d_in[11];
    const float* g_ic0   = (const float*)d_in[12];
    const float* b_ic0   = (const float*)d_in[13];
    const float* v_mu    = (const float*)d_in[14];
    const float* g_mu    = (const float*)d_in[15];
    const float* b_mu    = (const float*)d_in[16];
    const float* v_s2    = (const float*)d_in[17];
    const float* g_s2    = (const float*)d_in[18];
    const float* b_s2    = (const float*)d_in[19];
    float* out = (float*)d_out;

    __half *Wcat, *Wocat, *Wp, *hbuf, *hl, *embH, *ftH;
    float *bcat, *bocat, *pb, *c0;
    unsigned int* counters;
    cudaGetSymbolAddress((void**)&Wcat,     g_Wcat);
    cudaGetSymbolAddress((void**)&bcat,     g_bcat);
    cudaGetSymbolAddress((void**)&Wocat,    g_Wocat);
    cudaGetSymbolAddress((void**)&bocat,    g_bocat);
    cudaGetSymbolAddress((void**)&Wp,       g_Wp);
    cudaGetSymbolAddress((void**)&pb,       g_pb);
    cudaGetSymbolAddress((void**)&hbuf,     g_hbuf);
    cudaGetSymbolAddress((void**)&c0,       g_c0);
    cudaGetSymbolAddress((void**)&hl,       g_hl);
    cudaGetSymbolAddress((void**)&embH,     g_embH);
    cudaGetSymbolAddress((void**)&ftH,      g_ftH);
    cudaGetSymbolAddress((void**)&counters, g_counters);

    cudaFuncSetAttribute(hgemm,        cudaFuncAttributeMaxDynamicSharedMemorySize, SMEM_G);
    cudaFuncSetAttribute(lstm_persist, cudaFuncAttributeMaxDynamicSharedMemorySize, SMEM_P);

    cudaMemsetAsync(counters, 0, 8 * sizeof(unsigned int));

    wn_kernel<<<Hc, 256>>>(v_ih0, g_ih0, Wcat,            Ac);
    wn_kernel<<<Hc, 256>>>(v_ic0, g_ic0, Wcat + Hc * Ac,  Ac);
    wn_kernel<<<Lc, 256>>>(v_mu,  g_mu,  Wocat,           Hc);
    wn_kernel<<<Lc, 256>>>(v_s2,  g_s2,  Wocat + Lc * Hc, Hc);
    pack2<<<(2 * Hc + 255) / 256, 256>>>(b_ih0, b_ic0, bcat, Hc);
    pack2<<<(2 * Lc + 255) / 256, 256>>>(b_mu,  b_s2,  bocat, Lc);
    permute_kernel<<<Nw, 256>>>(W_hh, W_ih, b_ih, b_hh, Wp, pb);
    half_copy<<<(Vc * Ec + 255) / 256, 256>>>(embed, embH, Vc * Ec);
    half_copy<<<(Bc * Ac + 255) / 256, 256>>>(feat, ftH, Bc * Ac);

    // init: h0 (fp16, into hbuf[0]) and c0 (fp32), fused N=2048
    {
        dim3 grid(2 * Hc / 128, Bc / 128);   // (16, 8)
        hgemm<<<grid, 256, SMEM_G>>>(ftH, Ac, Ac / 32, Wcat, Ac, bcat,
                                     (float*)hbuf, Hc, 1, c0, Hc, 0, Hc);
    }

    // recurrence: ONE persistent kernel, per-bm-group barriers
    {
        dim3 grid(Nw / 128, Bc / 128);       // (32, 8) = 256 CTAs, 2/SM all resident
        lstm_persist<<<grid, 256, SMEM_P>>>(embH, cap, Wp, pb, c0, hbuf, hl, cap_len, counters);
    }

    // outputs: mu and sigma2 fused, N=512
    {
        dim3 grid(2 * Lc / 128, Bc / 128);   // (4, 8)
        hgemm<<<grid, 256, SMEM_G>>>(hl, Hc, Hc / 32, Wocat, Hc, bocat,
                                     out, Lc, 0, out + Bc * Lc, Lc, 0, Lc);
    }
}